// round 2
// baseline (speedup 1.0000x reference)
#include <cuda_runtime.h>
#include <cstdint>

// Problem dims (fixed by setup_inputs)
#define B_ 8
#define V_ 64
#define E_ 512
#define N_ 32
#define L_ 4
#define H_ 8
#define D_ 64
#define M_ 1024
#define R_ 128
#define HD_ 512
#define ROWS_ 512          // B*V
#define LHD_ 2048          // L*H*D
#define SROWS_ 16384       // B*V*N

// ---------------- scratch (__device__ globals; no allocation) ----------------
__device__ float g_wkt[E_ * LHD_];
__device__ float g_wvt[E_ * LHD_];
__device__ float g_keysf[ROWS_ * LHD_];
__device__ float g_valsf[ROWS_ * LHD_];
__device__ float g_att[ROWS_ * HD_];
__device__ float g_h1[ROWS_ * M_];
__device__ float g_h2[ROWS_ * M_];
__device__ float g_h3[ROWS_ * HD_];
__device__ float g_logits[ROWS_ * R_];

// ---------------- threefry2x32 (exact JAX semantics) ----------------
__host__ __device__ __forceinline__ uint32_t rotl32(uint32_t x, int r) {
    return (x << r) | (x >> (32 - r));
}
__host__ __device__ __forceinline__ void threefry2x32(
    uint32_t k0, uint32_t k1, uint32_t c0, uint32_t c1,
    uint32_t& o0, uint32_t& o1)
{
    uint32_t ks0 = k0, ks1 = k1, ks2 = k0 ^ k1 ^ 0x1BD11BDAu;
    uint32_t x0 = c0 + ks0, x1 = c1 + ks1;
#define TFR(r) { x0 += x1; x1 = rotl32(x1, r); x1 ^= x0; }
    TFR(13) TFR(15) TFR(26) TFR(6)
    x0 += ks1; x1 += ks2 + 1u;
    TFR(17) TFR(29) TFR(16) TFR(24)
    x0 += ks2; x1 += ks0 + 2u;
    TFR(13) TFR(15) TFR(26) TFR(6)
    x0 += ks0; x1 += ks1 + 3u;
    TFR(17) TFR(29) TFR(16) TFR(24)
    x0 += ks1; x1 += ks2 + 4u;
    TFR(13) TFR(15) TFR(26) TFR(6)
    x0 += ks2; x1 += ks0 + 5u;
#undef TFR
    o0 = x0; o1 = x1;
}

// Partitionable-mode random_bits for 32-bit output, counter = (0, i), XOR halves.
__device__ __forceinline__ uint32_t jax_random_bits32(uint32_t k0, uint32_t k1, uint32_t i) {
    uint32_t o0, o1;
    threefry2x32(k0, k1, 0u, i, o0, o1);
    return o0 ^ o1;
}

__device__ __forceinline__ float bits_to_unit_float(uint32_t bits) {
    // JAX uniform [0,1): bitcast(bits>>9 | 0x3f800000) - 1
    return __uint_as_float((bits >> 9) | 0x3f800000u) - 1.0f;
}

// ---------------- weight transpose: [L,H,E,D] -> [E, L*H*D] ----------------
__global__ void transpose_w_kernel(const float* __restrict__ in, float* __restrict__ out) {
    int i = blockIdx.x * 256 + threadIdx.x;      // over E_*LHD_ = 1048576
    if (i >= E_ * LHD_) return;
    int e    = i >> 11;          // /2048
    int rest = i & 2047;         // lh*64 + d
    int lh   = rest >> 6;
    int d    = rest & 63;
    out[i] = in[(lh * E_ + e) * D_ + d];
}

// ---------------- generic tiled SGEMM: C[ROWS,N] = A[ROWS,K] @ W[K,N] + bias ----------------
// block 16x16 threads, 64x64 tile, 4x4 microtile, BK=16
__global__ __launch_bounds__(256) void gemm_bias_kernel(
    const float* __restrict__ A, const float* __restrict__ W,
    const float* __restrict__ bias, float* __restrict__ C,
    int K, int N, int relu)
{
    __shared__ __align__(16) float As[16][64];
    __shared__ __align__(16) float Ws[16][64];
    int t = threadIdx.x;
    int row0 = blockIdx.y * 64, n0 = blockIdx.x * 64;
    int tx = t & 15, ty = t >> 4;
    int ar = t >> 2, ac = (t & 3) * 4;
    int wk = t >> 4, wn = (t & 15) * 4;
    float acc[4][4] = {};
    for (int k0 = 0; k0 < K; k0 += 16) {
        float4 av = *(const float4*)&A[(row0 + ar) * K + k0 + ac];
        As[ac + 0][ar] = av.x; As[ac + 1][ar] = av.y;
        As[ac + 2][ar] = av.z; As[ac + 3][ar] = av.w;
        float4 wv = *(const float4*)&W[(k0 + wk) * N + n0 + wn];
        *(float4*)&Ws[wk][wn] = wv;
        __syncthreads();
#pragma unroll
        for (int k = 0; k < 16; k++) {
            float a[4], b[4];
            *(float4*)a = *(const float4*)&As[k][ty * 4];
            *(float4*)b = *(const float4*)&Ws[k][tx * 4];
#pragma unroll
            for (int i = 0; i < 4; i++)
#pragma unroll
                for (int j = 0; j < 4; j++)
                    acc[i][j] = fmaf(a[i], b[j], acc[i][j]);
        }
        __syncthreads();
    }
#pragma unroll
    for (int i = 0; i < 4; i++) {
        int r = row0 + ty * 4 + i;
#pragma unroll
        for (int j = 0; j < 4; j++) {
            int n = n0 + tx * 4 + j;
            float v = acc[i][j] + bias[n];
            if (relu) v = fmaxf(v, 0.0f);
            C[r * N + n] = v;
        }
    }
}

// ---------------- block sum over 256 threads ----------------
__device__ __forceinline__ float block_sum256(float v, float* red) {
#pragma unroll
    for (int o = 16; o; o >>= 1) v += __shfl_xor_sync(0xffffffffu, v, o);
    int w = threadIdx.x >> 5;
    if ((threadIdx.x & 31) == 0) red[w] = v;
    __syncthreads();
    float tot = 0.0f;
#pragma unroll
    for (int k = 0; k < 8; k++) tot += red[k];
    __syncthreads();
    return tot;
}

// ---------------- attention + residual + LN1 (per (b,v) row) ----------------
__global__ __launch_bounds__(256) void attn_ln_kernel(
    const float* __restrict__ keysf, const float* __restrict__ valsf,
    float* __restrict__ att,
    const float* __restrict__ g, const float* __restrict__ b, int l)
{
    int row = blockIdx.x;             // 0..511 = b*V+v
    int bId = row >> 6;               // /V_
    int t = threadIdx.x;
    __shared__ float qs[HD_];
    __shared__ float sp[HD_];         // 8 heads x 64 weights
    __shared__ float red[8];

    qs[t]       = att[row * HD_ + t];
    qs[t + 256] = att[row * HD_ + t + 256];
    __syncthreads();

    int h = t >> 5, lane = t & 31;
    // scores + softmax: warp h handles head h, lane handles w=lane and lane+32
    float s[2];
#pragma unroll
    for (int ww = 0; ww < 2; ww++) {
        int w = lane + ww * 32;
        const float* kp = &keysf[(bId * V_ + w) * LHD_ + (l * H_ + h) * D_];
        float accv = 0.0f;
#pragma unroll
        for (int d = 0; d < 64; d++) accv = fmaf(qs[h * 64 + d], kp[d], accv);
        s[ww] = accv * 0.125f;        // D^-0.5
    }
    float mx = fmaxf(s[0], s[1]);
#pragma unroll
    for (int o = 16; o; o >>= 1) mx = fmaxf(mx, __shfl_xor_sync(0xffffffffu, mx, o));
    float e0 = expf(s[0] - mx), e1 = expf(s[1] - mx);
    float sum = e0 + e1;
#pragma unroll
    for (int o = 16; o; o >>= 1) sum += __shfl_xor_sync(0xffffffffu, sum, o);
    sp[h * 64 + lane]      = e0 / sum;
    sp[h * 64 + lane + 32] = e1 / sum;
    __syncthreads();

    // a = p @ vals ; residual r = att + a (two hd's per thread)
    float r[2];
#pragma unroll
    for (int rep = 0; rep < 2; rep++) {
        int hd = t + rep * 256;
        int hh = hd >> 6, d = hd & 63;
        const float* vp = &valsf[(bId * V_) * LHD_ + (l * H_ + hh) * D_ + d];
        float accv = 0.0f;
#pragma unroll
        for (int w = 0; w < 64; w++) accv = fmaf(sp[hh * 64 + w], vp[w * LHD_], accv);
        r[rep] = qs[hd] + accv;
    }
    __syncthreads();

    // layernorm over 512
    float m = block_sum256(r[0] + r[1], red) * (1.0f / 512.0f);
    float d0 = r[0] - m, d1 = r[1] - m;
    float v = block_sum256(d0 * d0 + d1 * d1, red) * (1.0f / 512.0f);
    float scale = 1.0f / sqrtf(v + 1e-5f);
    att[row * HD_ + t]       = d0 * scale * g[l * HD_ + t]       + b[l * HD_ + t];
    att[row * HD_ + t + 256] = d1 * scale * g[l * HD_ + t + 256] + b[l * HD_ + t + 256];
}

// ---------------- residual + LN2 ----------------
__global__ __launch_bounds__(256) void add_ln_kernel(
    const float* __restrict__ hbuf, float* __restrict__ att,
    const float* __restrict__ g, const float* __restrict__ b, int l)
{
    int row = blockIdx.x;
    int t = threadIdx.x;
    __shared__ float red[8];
    float x0 = att[row * HD_ + t]       + hbuf[row * HD_ + t];
    float x1 = att[row * HD_ + t + 256] + hbuf[row * HD_ + t + 256];
    float m = block_sum256(x0 + x1, red) * (1.0f / 512.0f);
    float d0 = x0 - m, d1 = x1 - m;
    float v = block_sum256(d0 * d0 + d1 * d1, red) * (1.0f / 512.0f);
    float scale = 1.0f / sqrtf(v + 1e-5f);
    att[row * HD_ + t]       = d0 * scale * g[l * HD_ + t]       + b[l * HD_ + t];
    att[row * HD_ + t + 256] = d1 * scale * g[l * HD_ + t + 256] + b[l * HD_ + t + 256];
}

// ---------------- fused gumbel + argmax + uniform + output ----------------
// one warp per (b,v,n) row; gumbel computed inline (partitionable threefry)
__global__ __launch_bounds__(256) void sample_kernel(
    const float* __restrict__ logits, float* __restrict__ out,
    uint32_t kc0, uint32_t kc1, uint32_t ku0, uint32_t ku1)
{
    int warp = threadIdx.x >> 5, lane = threadIdx.x & 31;
    int j = blockIdx.x * 8 + warp;            // row in [B,V,N] flat, 0..16383
    int bv = j >> 5;                          // /N_
    const float* lg = &logits[bv * R_];
    const float tiny = 1.17549435e-38f;
    float best = -__int_as_float(0x7f800000); // -inf
    int bidx = 0;
#pragma unroll
    for (int q = 0; q < 4; q++) {
        int r = lane + q * 32;
        uint32_t bits = jax_random_bits32(kc0, kc1, (uint32_t)(j * R_ + r));
        float u = fmaxf(bits_to_unit_float(bits), tiny);
        float gmb = -logf(-logf(u));
        float v = gmb + lg[r];
        if (v > best) { best = v; bidx = r; }
    }
#pragma unroll
    for (int o = 16; o; o >>= 1) {
        float ov = __shfl_xor_sync(0xffffffffu, best, o);
        int   oi = __shfl_xor_sync(0xffffffffu, bidx, o);
        if (ov > best || (ov == best && oi < bidx)) { best = ov; bidx = oi; }
    }
    if (lane == 0) {
        uint32_t bits = jax_random_bits32(ku0, ku1, (uint32_t)j);
        float u = bits_to_unit_float(bits);   // minval=0, maxval=1 -> exact
        out[j] = ((float)bidx + u) * (1.0f / 128.0f);
    }
}

// ---------------- launch ----------------
extern "C" void kernel_launch(void* const* d_in, const int* in_sizes, int n_in,
                              void* d_out, int out_size)
{
    // Primary assumption: inputs in setup_inputs dict order.
    int iflow = 0, iWshift = 1, ibshift = 2, iWk = 3, ibk = 4, iWv = 5, ibv = 6,
        iln1g = 7, iln1b = 8, iW1 = 9, ib1 = 10, iW2 = 11, ib2 = 12, iW3 = 13,
        ib3 = 14, iln2g = 15, iln2b = 16, iWdist = 17, ibdist = 18;
    // Fallback: alphabetical order (detect via first input size).
    if (in_sizes[0] == 2097152) {
        // W1,W2,W3,W_dist,W_shift,Wk,Wv,b1,b2,b3,b_dist,b_shift,bk,bv,flow,ln1_b,ln1_g,ln2_b,ln2_g
        iW1 = 0; iW2 = 1; iW3 = 2; iWdist = 3; iWshift = 4; iWk = 5; iWv = 6;
        ib1 = 7; ib2 = 8; ib3 = 9; ibdist = 10; ibshift = 11; ibk = 12; ibv = 13;
        iflow = 14; iln1b = 15; iln1g = 16; iln2b = 17; iln2g = 18;
    }

    const float* flow    = (const float*)d_in[iflow];
    const float* W_shift = (const float*)d_in[iWshift];
    const float* b_shift = (const float*)d_in[ibshift];
    const float* Wk      = (const float*)d_in[iWk];
    const float* bk      = (const float*)d_in[ibk];
    const float* Wv      = (const float*)d_in[iWv];
    const float* bv      = (const float*)d_in[ibv];
    const float* ln1_g   = (const float*)d_in[iln1g];
    const float* ln1_b   = (const float*)d_in[iln1b];
    const float* W1      = (const float*)d_in[iW1];
    const float* b1      = (const float*)d_in[ib1];
    const float* W2      = (const float*)d_in[iW2];
    const float* b2      = (const float*)d_in[ib2];
    const float* W3      = (const float*)d_in[iW3];
    const float* b3      = (const float*)d_in[ib3];
    const float* ln2_g   = (const float*)d_in[iln2g];
    const float* ln2_b   = (const float*)d_in[iln2b];
    const float* W_dist  = (const float*)d_in[iWdist];
    const float* b_dist  = (const float*)d_in[ibdist];

    float *wkt, *wvt, *keysf, *valsf, *att, *h1, *h2, *h3, *logits;
    cudaGetSymbolAddress((void**)&wkt,    g_wkt);
    cudaGetSymbolAddress((void**)&wvt,    g_wvt);
    cudaGetSymbolAddress((void**)&keysf,  g_keysf);
    cudaGetSymbolAddress((void**)&valsf,  g_valsf);
    cudaGetSymbolAddress((void**)&att,    g_att);
    cudaGetSymbolAddress((void**)&h1,     g_h1);
    cudaGetSymbolAddress((void**)&h2,     g_h2);
    cudaGetSymbolAddress((void**)&h3,     g_h3);
    cudaGetSymbolAddress((void**)&logits, g_logits);

    // JAX keys: key(1) = (0,1); kc = fold_in(key,0); ku = fold_in(key,1)
    // fold_in(key, d) = threefry2x32(key, counter=(0, d)) -> (o0, o1)
    uint32_t kc0, kc1, ku0, ku1;
    threefry2x32(0u, 1u, 0u, 0u, kc0, kc1);
    threefry2x32(0u, 1u, 0u, 1u, ku0, ku1);

    // weight transposes [L,H,E,D] -> [E, L*H*D]
    transpose_w_kernel<<<4096, 256>>>(Wk, wkt);
    transpose_w_kernel<<<4096, 256>>>(Wv, wvt);

    // keys/vals: [512,512] @ [512,2048] + bias
    gemm_bias_kernel<<<dim3(32, 8), 256>>>(flow, wkt, bk, keysf, E_, LHD_, 0);
    gemm_bias_kernel<<<dim3(32, 8), 256>>>(flow, wvt, bv, valsf, E_, LHD_, 0);

    // att0 = flow @ W_shift + b_shift
    gemm_bias_kernel<<<dim3(8, 8), 256>>>(flow, W_shift, b_shift, att, E_, HD_, 0);

    for (int l = 0; l < L_; l++) {
        attn_ln_kernel<<<ROWS_, 256>>>(keysf, valsf, att, ln1_g, ln1_b, l);
        gemm_bias_kernel<<<dim3(16, 8), 256>>>(att, W1 + (size_t)l * HD_ * M_,
                                               b1 + l * M_, h1, HD_, M_, 1);
        gemm_bias_kernel<<<dim3(16, 8), 256>>>(h1, W2 + (size_t)l * M_ * M_,
                                               b2 + l * M_, h2, M_, M_, 1);
        gemm_bias_kernel<<<dim3(8, 8), 256>>>(h2, W3 + (size_t)l * M_ * HD_,
                                              b3 + l * HD_, h3, M_, HD_, 0);
        add_ln_kernel<<<ROWS_, 256>>>(h3, att, ln2_g, ln2_b, l);
    }

    // logits = att @ W_dist + b_dist
    gemm_bias_kernel<<<dim3(2, 8), 256>>>(att, W_dist, b_dist, logits, HD_, R_, 0);

    // fused gumbel + sample
    sample_kernel<<<2048, 256>>>(logits, (float*)d_out, kc0, kc1, ku0, ku1);
}

// round 3
// speedup vs baseline: 1.4917x; 1.4917x over previous
#include <cuda_runtime.h>
#include <cstdint>

// Problem dims (fixed by setup_inputs)
#define B_ 8
#define V_ 64
#define E_ 512
#define N_ 32
#define L_ 4
#define H_ 8
#define D_ 64
#define M_ 1024
#define R_ 128
#define HD_ 512
#define ROWS_ 512          // B*V
#define LHD_ 2048          // L*H*D
#define SROWS_ 16384       // B*V*N

// ---------------- scratch (__device__ globals; no allocation) ----------------
__device__ __align__(16) float g_keysf[ROWS_ * LHD_];
__device__ __align__(16) float g_valsf[ROWS_ * LHD_];
__device__ __align__(16) float g_att[ROWS_ * HD_];
__device__ __align__(16) float g_h1[ROWS_ * M_];
__device__ __align__(16) float g_h2[ROWS_ * M_];
__device__ __align__(16) float g_h3[2 * ROWS_ * HD_];     // 2 split-K partials
__device__ __align__(16) float g_logits[4 * ROWS_ * R_];  // 4 split-K partials

// ---------------- threefry2x32 (exact JAX semantics) ----------------
__host__ __device__ __forceinline__ uint32_t rotl32(uint32_t x, int r) {
    return (x << r) | (x >> (32 - r));
}
__host__ __device__ __forceinline__ void threefry2x32(
    uint32_t k0, uint32_t k1, uint32_t c0, uint32_t c1,
    uint32_t& o0, uint32_t& o1)
{
    uint32_t ks0 = k0, ks1 = k1, ks2 = k0 ^ k1 ^ 0x1BD11BDAu;
    uint32_t x0 = c0 + ks0, x1 = c1 + ks1;
#define TFR(r) { x0 += x1; x1 = rotl32(x1, r); x1 ^= x0; }
    TFR(13) TFR(15) TFR(26) TFR(6)
    x0 += ks1; x1 += ks2 + 1u;
    TFR(17) TFR(29) TFR(16) TFR(24)
    x0 += ks2; x1 += ks0 + 2u;
    TFR(13) TFR(15) TFR(26) TFR(6)
    x0 += ks0; x1 += ks1 + 3u;
    TFR(17) TFR(29) TFR(16) TFR(24)
    x0 += ks1; x1 += ks2 + 4u;
    TFR(13) TFR(15) TFR(26) TFR(6)
    x0 += ks2; x1 += ks0 + 5u;
#undef TFR
    o0 = x0; o1 = x1;
}

// Partitionable-mode random_bits for 32-bit output, counter = (0, i), XOR halves.
__device__ __forceinline__ uint32_t jax_random_bits32(uint32_t k0, uint32_t k1, uint32_t i) {
    uint32_t o0, o1;
    threefry2x32(k0, k1, 0u, i, o0, o1);
    return o0 ^ o1;
}

__device__ __forceinline__ float bits_to_unit_float(uint32_t bits) {
    return __uint_as_float((bits >> 9) | 0x3f800000u) - 1.0f;
}

// ---------------- double-buffered SGEMM body: 64x64 tile, BK=32 ----------------
// As stored transposed [k][row] (padded row 68), Ws [k][n].
__device__ __forceinline__ void gemm_body(
    float (*As)[32][68], float (*Ws)[32][64],
    const float* __restrict__ A, int lda,
    const float* __restrict__ Wb, int wStride,
    const float* __restrict__ bias, int useBias,
    float* __restrict__ C, int ldc,
    int row0, int n0, int kStart, int kLen, int relu)
{
    const int t  = threadIdx.x;
    const int tx = t & 15, ty = t >> 4;
    const int ar = t >> 3, ac = (t & 7) << 2;
    const int wk = t >> 4, wn = (t & 15) << 2;

    const float* Ap = A + (row0 + ar) * lda + kStart + ac;
    const float* Wp = Wb + (kStart + wk) * wStride + wn;

    float4 a0 = *(const float4*)Ap;
    float4 a1 = *(const float4*)(Ap + 32 * lda);
    float4 w0 = *(const float4*)Wp;
    float4 w1 = *(const float4*)(Wp + 16 * wStride);

    As[0][ac + 0][ar] = a0.x; As[0][ac + 1][ar] = a0.y;
    As[0][ac + 2][ar] = a0.z; As[0][ac + 3][ar] = a0.w;
    As[0][ac + 0][ar + 32] = a1.x; As[0][ac + 1][ar + 32] = a1.y;
    As[0][ac + 2][ar + 32] = a1.z; As[0][ac + 3][ar + 32] = a1.w;
    *(float4*)&Ws[0][wk][wn]      = w0;
    *(float4*)&Ws[0][wk + 16][wn] = w1;
    __syncthreads();

    float acc[4][4] = {};
    const int nIter = kLen >> 5;
    int buf = 0;
    for (int it = 0; it < nIter; ++it) {
        if (it + 1 < nIter) {
            const float* Ap2 = Ap + ((it + 1) << 5);
            a0 = *(const float4*)Ap2;
            a1 = *(const float4*)(Ap2 + 32 * lda);
            const float* Wp2 = Wp + ((it + 1) << 5) * wStride;
            w0 = *(const float4*)Wp2;
            w1 = *(const float4*)(Wp2 + 16 * wStride);
        }
#pragma unroll
        for (int k = 0; k < 32; ++k) {
            float av[4], bv[4];
            *(float4*)av = *(const float4*)&As[buf][k][ty << 2];
            *(float4*)bv = *(const float4*)&Ws[buf][k][tx << 2];
#pragma unroll
            for (int i = 0; i < 4; i++)
#pragma unroll
                for (int j = 0; j < 4; j++)
                    acc[i][j] = fmaf(av[i], bv[j], acc[i][j]);
        }
        if (it + 1 < nIter) {
            int nb = buf ^ 1;
            As[nb][ac + 0][ar] = a0.x; As[nb][ac + 1][ar] = a0.y;
            As[nb][ac + 2][ar] = a0.z; As[nb][ac + 3][ar] = a0.w;
            As[nb][ac + 0][ar + 32] = a1.x; As[nb][ac + 1][ar + 32] = a1.y;
            As[nb][ac + 2][ar + 32] = a1.z; As[nb][ac + 3][ar + 32] = a1.w;
            *(float4*)&Ws[nb][wk][wn]      = w0;
            *(float4*)&Ws[nb][wk + 16][wn] = w1;
            __syncthreads();
            buf = nb;
        }
    }
#pragma unroll
    for (int i = 0; i < 4; i++) {
        int r = row0 + (ty << 2) + i;
        float4 v;
        float* vp = &v.x;
#pragma unroll
        for (int j = 0; j < 4; j++) {
            int n = n0 + (tx << 2) + j;
            float x = acc[i][j];
            if (useBias) x += bias[n];
            if (relu) x = fmaxf(x, 0.0f);
            vp[j] = x;
        }
        *(float4*)&C[r * ldc + n0 + (tx << 2)] = v;
    }
}

// ---------------- generic GEMM kernel (with optional split-K via grid.z) ----------------
__global__ __launch_bounds__(256) void gemm_generic(
    const float* __restrict__ A, const float* __restrict__ W,
    const float* __restrict__ bias, float* __restrict__ C,
    int K, int N, int relu)
{
    __shared__ float As[2][32][68];
    __shared__ float Ws[2][32][64];
    int row0 = blockIdx.y << 6, n0 = blockIdx.x << 6;
    int z = blockIdx.z;
    int kLen = K / gridDim.z;
    float* Cz = C + z * ((gridDim.y << 6) * N);
    gemm_body(As, Ws, A, K, W + n0, N, bias, (z == 0) ? 1 : 0,
              Cz, N, row0, n0, z * kLen, kLen, relu);
}

// ---------------- merged keys/vals/att0 kernel (576 blocks) ----------------
__global__ __launch_bounds__(256) void qkv_kernel(
    const float* __restrict__ flow,
    const float* __restrict__ Wk, const float* __restrict__ bk,
    const float* __restrict__ Wv, const float* __restrict__ bv,
    const float* __restrict__ Wsh, const float* __restrict__ bsh,
    float* __restrict__ keys, float* __restrict__ vals, float* __restrict__ att)
{
    __shared__ float As[2][32][68];
    __shared__ float Ws[2][32][64];
    int bid = blockIdx.x;
    const float* Wbase; const float* bias; float* C;
    int wStride, Ncols, row0, n0;
    if (bid < 512) {
        int isV = bid >> 8;
        int j = bid & 255;
        int nt = j & 31, rt = j >> 5;
        n0 = nt << 6; row0 = rt << 6;
        const float* Wsel = isV ? Wv : Wk;           // [L*H][E][64]
        Wbase = Wsel + nt * (E_ * 64);
        wStride = 64;
        bias = isV ? bv : bk;
        C = isV ? vals : keys;
        Ncols = LHD_;
    } else {
        int j = bid - 512;
        int nt = j & 7, rt = j >> 3;
        n0 = nt << 6; row0 = rt << 6;
        Wbase = Wsh + n0; wStride = HD_;
        bias = bsh; C = att; Ncols = HD_;
    }
    gemm_body(As, Ws, flow, E_, Wbase, wStride, bias, 1,
              C, Ncols, row0, n0, 0, E_, 0);
}

// ---------------- block sum over 256 threads ----------------
__device__ __forceinline__ float block_sum256(float v, float* red) {
#pragma unroll
    for (int o = 16; o; o >>= 1) v += __shfl_xor_sync(0xffffffffu, v, o);
    int w = threadIdx.x >> 5;
    if ((threadIdx.x & 31) == 0) red[w] = v;
    __syncthreads();
    float tot = 0.0f;
#pragma unroll
    for (int k = 0; k < 8; k++) tot += red[k];
    __syncthreads();
    return tot;
}

// ---------------- attention + residual + LN1 (per (b,v) row) ----------------
__global__ __launch_bounds__(256) void attn_ln_kernel(
    const float* __restrict__ keysf, const float* __restrict__ valsf,
    float* __restrict__ att,
    const float* __restrict__ g, const float* __restrict__ b, int l)
{
    int row = blockIdx.x;             // 0..511 = b*V+v
    int bId = row >> 6;
    int t = threadIdx.x;
    __shared__ float qs[HD_];
    __shared__ float sp[HD_];
    __shared__ float red[8];

    qs[t]       = att[row * HD_ + t];
    qs[t + 256] = att[row * HD_ + t + 256];
    __syncthreads();

    int h = t >> 5, lane = t & 31;
    float s[2];
#pragma unroll
    for (int ww = 0; ww < 2; ww++) {
        int w = lane + ww * 32;
        const float* kp = &keysf[(bId * V_ + w) * LHD_ + (l * H_ + h) * D_];
        float accv = 0.0f;
#pragma unroll
        for (int d = 0; d < 64; d++) accv = fmaf(qs[h * 64 + d], kp[d], accv);
        s[ww] = accv * 0.125f;
    }
    float mx = fmaxf(s[0], s[1]);
#pragma unroll
    for (int o = 16; o; o >>= 1) mx = fmaxf(mx, __shfl_xor_sync(0xffffffffu, mx, o));
    float e0 = expf(s[0] - mx), e1 = expf(s[1] - mx);
    float sum = e0 + e1;
#pragma unroll
    for (int o = 16; o; o >>= 1) sum += __shfl_xor_sync(0xffffffffu, sum, o);
    sp[h * 64 + lane]      = e0 / sum;
    sp[h * 64 + lane + 32] = e1 / sum;
    __syncthreads();

    float r[2];
#pragma unroll
    for (int rep = 0; rep < 2; rep++) {
        int hd = t + rep * 256;
        int hh = hd >> 6, d = hd & 63;
        const float* vp = &valsf[(bId * V_) * LHD_ + (l * H_ + hh) * D_ + d];
        float accv = 0.0f;
#pragma unroll
        for (int w = 0; w < 64; w++) accv = fmaf(sp[hh * 64 + w], vp[w * LHD_], accv);
        r[rep] = qs[hd] + accv;
    }
    __syncthreads();

    float m = block_sum256(r[0] + r[1], red) * (1.0f / 512.0f);
    float d0 = r[0] - m, d1 = r[1] - m;
    float v = block_sum256(d0 * d0 + d1 * d1, red) * (1.0f / 512.0f);
    float scale = 1.0f / sqrtf(v + 1e-5f);
    att[row * HD_ + t]       = d0 * scale * g[l * HD_ + t]       + b[l * HD_ + t];
    att[row * HD_ + t + 256] = d1 * scale * g[l * HD_ + t + 256] + b[l * HD_ + t + 256];
}

// ---------------- residual (2 split-K partials) + LN2 ----------------
__global__ __launch_bounds__(256) void add_ln_kernel(
    const float* __restrict__ p0, const float* __restrict__ p1,
    float* __restrict__ att,
    const float* __restrict__ g, const float* __restrict__ b, int l)
{
    int row = blockIdx.x;
    int t = threadIdx.x;
    __shared__ float red[8];
    float x0 = att[row * HD_ + t]       + (p0[row * HD_ + t]       + p1[row * HD_ + t]);
    float x1 = att[row * HD_ + t + 256] + (p0[row * HD_ + t + 256] + p1[row * HD_ + t + 256]);
    float m = block_sum256(x0 + x1, red) * (1.0f / 512.0f);
    float d0 = x0 - m, d1 = x1 - m;
    float v = block_sum256(d0 * d0 + d1 * d1, red) * (1.0f / 512.0f);
    float scale = 1.0f / sqrtf(v + 1e-5f);
    att[row * HD_ + t]       = d0 * scale * g[l * HD_ + t]       + b[l * HD_ + t];
    att[row * HD_ + t + 256] = d1 * scale * g[l * HD_ + t + 256] + b[l * HD_ + t + 256];
}

// ---------------- fused gumbel + argmax + uniform + output ----------------
__global__ __launch_bounds__(256) void sample_kernel(
    const float* __restrict__ logits, float* __restrict__ out,
    uint32_t kc0, uint32_t kc1, uint32_t ku0, uint32_t ku1)
{
    int warp = threadIdx.x >> 5, lane = threadIdx.x & 31;
    int j = blockIdx.x * 8 + warp;            // row in [B,V,N] flat, 0..16383
    int bv = j >> 5;
    const float* lg0 = &logits[bv * R_];
    const float* lg1 = lg0 + ROWS_ * R_;
    const float* lg2 = lg1 + ROWS_ * R_;
    const float* lg3 = lg2 + ROWS_ * R_;
    const float tiny = 1.17549435e-38f;
    float best = -__int_as_float(0x7f800000);
    int bidx = 0;
#pragma unroll
    for (int q = 0; q < 4; q++) {
        int r = lane + q * 32;
        float lgv = ((lg0[r] + lg1[r]) + lg2[r]) + lg3[r];
        uint32_t bits = jax_random_bits32(kc0, kc1, (uint32_t)(j * R_ + r));
        float u = fmaxf(bits_to_unit_float(bits), tiny);
        float gmb = -logf(-logf(u));
        float v = gmb + lgv;
        if (v > best) { best = v; bidx = r; }
    }
#pragma unroll
    for (int o = 16; o; o >>= 1) {
        float ov = __shfl_xor_sync(0xffffffffu, best, o);
        int   oi = __shfl_xor_sync(0xffffffffu, bidx, o);
        if (ov > best || (ov == best && oi < bidx)) { best = ov; bidx = oi; }
    }
    if (lane == 0) {
        uint32_t bits = jax_random_bits32(ku0, ku1, (uint32_t)j);
        float u = bits_to_unit_float(bits);
        out[j] = ((float)bidx + u) * (1.0f / 128.0f);
    }
}

// ---------------- launch ----------------
extern "C" void kernel_launch(void* const* d_in, const int* in_sizes, int n_in,
                              void* d_out, int out_size)
{
    int iflow = 0, iWshift = 1, ibshift = 2, iWk = 3, ibk = 4, iWv = 5, ibv = 6,
        iln1g = 7, iln1b = 8, iW1 = 9, ib1 = 10, iW2 = 11, ib2 = 12, iW3 = 13,
        ib3 = 14, iln2g = 15, iln2b = 16, iWdist = 17, ibdist = 18;
    if (in_sizes[0] == 2097152) {   // alphabetical fallback
        iW1 = 0; iW2 = 1; iW3 = 2; iWdist = 3; iWshift = 4; iWk = 5; iWv = 6;
        ib1 = 7; ib2 = 8; ib3 = 9; ibdist = 10; ibshift = 11; ibk = 12; ibv = 13;
        iflow = 14; iln1b = 15; iln1g = 16; iln2b = 17; iln2g = 18;
    }

    const float* flow    = (const float*)d_in[iflow];
    const float* W_shift = (const float*)d_in[iWshift];
    const float* b_shift = (const float*)d_in[ibshift];
    const float* Wk      = (const float*)d_in[iWk];
    const float* bk      = (const float*)d_in[ibk];
    const float* Wv      = (const float*)d_in[iWv];
    const float* bv      = (const float*)d_in[ibv];
    const float* ln1_g   = (const float*)d_in[iln1g];
    const float* ln1_b   = (const float*)d_in[iln1b];
    const float* W1      = (const float*)d_in[iW1];
    const float* b1      = (const float*)d_in[ib1];
    const float* W2      = (const float*)d_in[iW2];
    const float* b2      = (const float*)d_in[ib2];
    const float* W3      = (const float*)d_in[iW3];
    const float* b3      = (const float*)d_in[ib3];
    const float* ln2_g   = (const float*)d_in[iln2g];
    const float* ln2_b   = (const float*)d_in[iln2b];
    const float* W_dist  = (const float*)d_in[iWdist];
    const float* b_dist  = (const float*)d_in[ibdist];

    float *keysf, *valsf, *att, *h1, *h2, *h3, *logits;
    cudaGetSymbolAddress((void**)&keysf,  g_keysf);
    cudaGetSymbolAddress((void**)&valsf,  g_valsf);
    cudaGetSymbolAddress((void**)&att,    g_att);
    cudaGetSymbolAddress((void**)&h1,     g_h1);
    cudaGetSymbolAddress((void**)&h2,     g_h2);
    cudaGetSymbolAddress((void**)&h3,     g_h3);
    cudaGetSymbolAddress((void**)&logits, g_logits);

    uint32_t kc0, kc1, ku0, ku1;
    threefry2x32(0u, 1u, 0u, 0u, kc0, kc1);
    threefry2x32(0u, 1u, 0u, 1u, ku0, ku1);

    // keys + vals + att0 in one launch (576 blocks), transposes folded into B-indexing
    qkv_kernel<<<576, 256>>>(flow, Wk, bk, Wv, bv, W_shift, b_shift,
                             keysf, valsf, att);

    for (int l = 0; l < L_; l++) {
        attn_ln_kernel<<<ROWS_, 256>>>(keysf, valsf, att, ln1_g, ln1_b, l);
        gemm_generic<<<dim3(16, 8, 1), 256>>>(att, W1 + (size_t)l * HD_ * M_,
                                              b1 + l * M_, h1, HD_, M_, 1);
        gemm_generic<<<dim3(16, 8, 1), 256>>>(h1, W2 + (size_t)l * M_ * M_,
                                              b2 + l * M_, h2, M_, M_, 1);
        gemm_generic<<<dim3(8, 8, 2), 256>>>(h2, W3 + (size_t)l * M_ * HD_,
                                             b3 + l * HD_, h3, M_, HD_, 0);
        add_ln_kernel<<<ROWS_, 256>>>(h3, h3 + ROWS_ * HD_, att, ln2_g, ln2_b, l);
    }

    // logits with split-K=4 (partials summed in sample_kernel)
    gemm_generic<<<dim3(2, 8, 4), 256>>>(att, W_dist, b_dist, logits, HD_, R_, 0);

    sample_kernel<<<2048, 256>>>(logits, (float*)d_out, kc0, kc1, ku0, ku1);
}

// round 4
// speedup vs baseline: 1.5027x; 1.0074x over previous
#include <cuda_runtime.h>
#include <cstdint>

// Problem dims (fixed by setup_inputs)
#define B_ 8
#define V_ 64
#define E_ 512
#define N_ 32
#define L_ 4
#define H_ 8
#define D_ 64
#define M_ 1024
#define R_ 128
#define HD_ 512
#define ROWS_ 512          // B*V
#define LHD_ 2048          // L*H*D
#define SROWS_ 16384       // B*V*N

// ---------------- scratch (__device__ globals; no allocation) ----------------
__device__ __align__(16) float g_keysf[ROWS_ * LHD_];
__device__ __align__(16) float g_valsf[ROWS_ * LHD_];
__device__ __align__(16) float g_att[ROWS_ * HD_];
__device__ __align__(16) float g_h1[2 * ROWS_ * M_];      // 2 split-K partials
__device__ __align__(16) float g_h2[2 * ROWS_ * M_];      // 2 split-K partials
__device__ __align__(16) float g_h3[4 * ROWS_ * HD_];     // 4 split-K partials
__device__ __align__(16) float g_logits[4 * ROWS_ * R_];  // 4 split-K partials

// ---------------- threefry2x32 (exact JAX semantics) ----------------
__host__ __device__ __forceinline__ uint32_t rotl32(uint32_t x, int r) {
    return (x << r) | (x >> (32 - r));
}
__host__ __device__ __forceinline__ void threefry2x32(
    uint32_t k0, uint32_t k1, uint32_t c0, uint32_t c1,
    uint32_t& o0, uint32_t& o1)
{
    uint32_t ks0 = k0, ks1 = k1, ks2 = k0 ^ k1 ^ 0x1BD11BDAu;
    uint32_t x0 = c0 + ks0, x1 = c1 + ks1;
#define TFR(r) { x0 += x1; x1 = rotl32(x1, r); x1 ^= x0; }
    TFR(13) TFR(15) TFR(26) TFR(6)
    x0 += ks1; x1 += ks2 + 1u;
    TFR(17) TFR(29) TFR(16) TFR(24)
    x0 += ks2; x1 += ks0 + 2u;
    TFR(13) TFR(15) TFR(26) TFR(6)
    x0 += ks0; x1 += ks1 + 3u;
    TFR(17) TFR(29) TFR(16) TFR(24)
    x0 += ks1; x1 += ks2 + 4u;
    TFR(13) TFR(15) TFR(26) TFR(6)
    x0 += ks2; x1 += ks0 + 5u;
#undef TFR
    o0 = x0; o1 = x1;
}

__device__ __forceinline__ uint32_t jax_random_bits32(uint32_t k0, uint32_t k1, uint32_t i) {
    uint32_t o0, o1;
    threefry2x32(k0, k1, 0u, i, o0, o1);
    return o0 ^ o1;
}

__device__ __forceinline__ float bits_to_unit_float(uint32_t bits) {
    return __uint_as_float((bits >> 9) | 0x3f800000u) - 1.0f;
}

// ---------------- A-load: plain, or fused relu(p0 + p1) of split-K partials ----------------
__device__ __forceinline__ float4 loadA(const float* __restrict__ p0,
                                        const float* __restrict__ p1,
                                        int offs)
{
    float4 a = *(const float4*)&p0[offs];
    if (p1) {
        float4 b = *(const float4*)&p1[offs];
        a.x = fmaxf(a.x + b.x, 0.0f);
        a.y = fmaxf(a.y + b.y, 0.0f);
        a.z = fmaxf(a.z + b.z, 0.0f);
        a.w = fmaxf(a.w + b.w, 0.0f);
    }
    return a;
}

// ---------------- double-buffered SGEMM body: 64x64 tile, BK=32 ----------------
__device__ __forceinline__ void gemm_body(
    float (*As)[32][68], float (*Ws)[32][64],
    const float* __restrict__ A, const float* __restrict__ A2, int lda,
    const float* __restrict__ Wb, int wStride,
    const float* __restrict__ bias, int useBias,
    float* __restrict__ C, int ldc,
    int row0, int n0, int kStart, int kLen, int relu)
{
    const int t  = threadIdx.x;
    const int tx = t & 15, ty = t >> 4;
    const int ar = t >> 3, ac = (t & 7) << 2;
    const int wk = t >> 4, wn = (t & 15) << 2;

    const int aOff = (row0 + ar) * lda + kStart + ac;
    const float* Wp = Wb + (kStart + wk) * wStride + wn;

    float4 a0 = loadA(A, A2, aOff);
    float4 a1 = loadA(A, A2, aOff + 32 * lda);
    float4 w0 = *(const float4*)Wp;
    float4 w1 = *(const float4*)(Wp + 16 * wStride);

    As[0][ac + 0][ar] = a0.x; As[0][ac + 1][ar] = a0.y;
    As[0][ac + 2][ar] = a0.z; As[0][ac + 3][ar] = a0.w;
    As[0][ac + 0][ar + 32] = a1.x; As[0][ac + 1][ar + 32] = a1.y;
    As[0][ac + 2][ar + 32] = a1.z; As[0][ac + 3][ar + 32] = a1.w;
    *(float4*)&Ws[0][wk][wn]      = w0;
    *(float4*)&Ws[0][wk + 16][wn] = w1;
    __syncthreads();

    float acc[4][4] = {};
    const int nIter = kLen >> 5;
    int buf = 0;
    for (int it = 0; it < nIter; ++it) {
        if (it + 1 < nIter) {
            int off2 = aOff + ((it + 1) << 5);
            a0 = loadA(A, A2, off2);
            a1 = loadA(A, A2, off2 + 32 * lda);
            const float* Wp2 = Wp + ((it + 1) << 5) * wStride;
            w0 = *(const float4*)Wp2;
            w1 = *(const float4*)(Wp2 + 16 * wStride);
        }
#pragma unroll
        for (int k = 0; k < 32; ++k) {
            float av[4], bv[4];
            *(float4*)av = *(const float4*)&As[buf][k][ty << 2];
            *(float4*)bv = *(const float4*)&Ws[buf][k][tx << 2];
#pragma unroll
            for (int i = 0; i < 4; i++)
#pragma unroll
                for (int j = 0; j < 4; j++)
                    acc[i][j] = fmaf(av[i], bv[j], acc[i][j]);
        }
        if (it + 1 < nIter) {
            int nb = buf ^ 1;
            As[nb][ac + 0][ar] = a0.x; As[nb][ac + 1][ar] = a0.y;
            As[nb][ac + 2][ar] = a0.z; As[nb][ac + 3][ar] = a0.w;
            As[nb][ac + 0][ar + 32] = a1.x; As[nb][ac + 1][ar + 32] = a1.y;
            As[nb][ac + 2][ar + 32] = a1.z; As[nb][ac + 3][ar + 32] = a1.w;
            *(float4*)&Ws[nb][wk][wn]      = w0;
            *(float4*)&Ws[nb][wk + 16][wn] = w1;
            __syncthreads();
            buf = nb;
        }
    }
#pragma unroll
    for (int i = 0; i < 4; i++) {
        int r = row0 + (ty << 2) + i;
        float4 v;
        float* vp = &v.x;
#pragma unroll
        for (int j = 0; j < 4; j++) {
            int n = n0 + (tx << 2) + j;
            float x = acc[i][j];
            if (useBias) x += bias[n];
            if (relu) x = fmaxf(x, 0.0f);
            vp[j] = x;
        }
        *(float4*)&C[r * ldc + n0 + (tx << 2)] = v;
    }
}

// ---------------- generic GEMM kernel (split-K via grid.z; A may be 2 partials) ----------------
// If A2 != null: A_effective = relu(A + A2) elementwise (bias already inside z0 partial).
__global__ __launch_bounds__(256) void gemm_generic(
    const float* __restrict__ A, const float* __restrict__ A2,
    const float* __restrict__ W,
    const float* __restrict__ bias, float* __restrict__ C,
    int K, int N)
{
    __shared__ float As[2][32][68];
    __shared__ float Ws[2][32][64];
    int row0 = blockIdx.y << 6, n0 = blockIdx.x << 6;
    int z = blockIdx.z;
    int kLen = K / gridDim.z;
    float* Cz = C + z * ((gridDim.y << 6) * N);
    gemm_body(As, Ws, A, A2, K, W + n0, N, bias, (z == 0) ? 1 : 0,
              Cz, N, row0, n0, z * kLen, kLen, 0);
}

// ---------------- merged keys/vals/att0 kernel (576 blocks) ----------------
__global__ __launch_bounds__(256) void qkv_kernel(
    const float* __restrict__ flow,
    const float* __restrict__ Wk, const float* __restrict__ bk,
    const float* __restrict__ Wv, const float* __restrict__ bv,
    const float* __restrict__ Wsh, const float* __restrict__ bsh,
    float* __restrict__ keys, float* __restrict__ vals, float* __restrict__ att)
{
    __shared__ float As[2][32][68];
    __shared__ float Ws[2][32][64];
    int bid = blockIdx.x;
    const float* Wbase; const float* bias; float* C;
    int wStride, Ncols, row0, n0;
    if (bid < 512) {
        int isV = bid >> 8;
        int j = bid & 255;
        int nt = j & 31, rt = j >> 5;
        n0 = nt << 6; row0 = rt << 6;
        const float* Wsel = isV ? Wv : Wk;           // [L*H][E][64]
        Wbase = Wsel + nt * (E_ * 64);
        wStride = 64;
        bias = isV ? bv : bk;
        C = isV ? vals : keys;
        Ncols = LHD_;
    } else {
        int j = bid - 512;
        int nt = j & 7, rt = j >> 3;
        n0 = nt << 6; row0 = rt << 6;
        Wbase = Wsh + n0; wStride = HD_;
        bias = bsh; C = att; Ncols = HD_;
    }
    gemm_body(As, Ws, flow, nullptr, E_, Wbase, wStride, bias, 1,
              C, Ncols, row0, n0, 0, E_, 0);
}

// ---------------- block sum over 256 threads ----------------
__device__ __forceinline__ float block_sum256(float v, float* red) {
#pragma unroll
    for (int o = 16; o; o >>= 1) v += __shfl_xor_sync(0xffffffffu, v, o);
    int w = threadIdx.x >> 5;
    if ((threadIdx.x & 31) == 0) red[w] = v;
    __syncthreads();
    float tot = 0.0f;
#pragma unroll
    for (int k = 0; k < 8; k++) tot += red[k];
    __syncthreads();
    return tot;
}

// ---------------- attention + residual + LN1 (per (b,v) row) ----------------
__global__ __launch_bounds__(256) void attn_ln_kernel(
    const float* __restrict__ keysf, const float* __restrict__ valsf,
    float* __restrict__ att,
    const float* __restrict__ g, const float* __restrict__ b, int l)
{
    int row = blockIdx.x;             // 0..511 = b*V+v
    int bId = row >> 6;
    int t = threadIdx.x;
    __shared__ float qs[HD_];
    __shared__ float sp[HD_];
    __shared__ float red[8];

    qs[t]       = att[row * HD_ + t];
    qs[t + 256] = att[row * HD_ + t + 256];
    __syncthreads();

    int h = t >> 5, lane = t & 31;
    float s[2];
#pragma unroll
    for (int ww = 0; ww < 2; ww++) {
        int w = lane + ww * 32;
        const float* kp = &keysf[(bId * V_ + w) * LHD_ + (l * H_ + h) * D_];
        float accv = 0.0f;
#pragma unroll
        for (int d = 0; d < 64; d++) accv = fmaf(qs[h * 64 + d], kp[d], accv);
        s[ww] = accv * 0.125f;
    }
    float mx = fmaxf(s[0], s[1]);
#pragma unroll
    for (int o = 16; o; o >>= 1) mx = fmaxf(mx, __shfl_xor_sync(0xffffffffu, mx, o));
    float e0 = expf(s[0] - mx), e1 = expf(s[1] - mx);
    float sum = e0 + e1;
#pragma unroll
    for (int o = 16; o; o >>= 1) sum += __shfl_xor_sync(0xffffffffu, sum, o);
    sp[h * 64 + lane]      = e0 / sum;
    sp[h * 64 + lane + 32] = e1 / sum;
    __syncthreads();

    float r[2];
#pragma unroll
    for (int rep = 0; rep < 2; rep++) {
        int hd = t + rep * 256;
        int hh = hd >> 6, d = hd & 63;
        const float* vp = &valsf[(bId * V_) * LHD_ + (l * H_ + hh) * D_ + d];
        float accv = 0.0f;
#pragma unroll
        for (int w = 0; w < 64; w++) accv = fmaf(sp[hh * 64 + w], vp[w * LHD_], accv);
        r[rep] = qs[hd] + accv;
    }
    __syncthreads();

    float m = block_sum256(r[0] + r[1], red) * (1.0f / 512.0f);
    float d0 = r[0] - m, d1 = r[1] - m;
    float v = block_sum256(d0 * d0 + d1 * d1, red) * (1.0f / 512.0f);
    float scale = 1.0f / sqrtf(v + 1e-5f);
    att[row * HD_ + t]       = d0 * scale * g[l * HD_ + t]       + b[l * HD_ + t];
    att[row * HD_ + t + 256] = d1 * scale * g[l * HD_ + t + 256] + b[l * HD_ + t + 256];
}

// ---------------- residual (4 split-K partials) + LN2 ----------------
__global__ __launch_bounds__(256) void add_ln_kernel(
    const float* __restrict__ p, float* __restrict__ att,
    const float* __restrict__ g, const float* __restrict__ b, int l)
{
    int row = blockIdx.x;
    int t = threadIdx.x;
    __shared__ float red[8];
    const int S = ROWS_ * HD_;
    int i0 = row * HD_ + t, i1 = i0 + 256;
    float x0 = att[i0] + ((p[i0] + p[i0 + S]) + (p[i0 + 2 * S] + p[i0 + 3 * S]));
    float x1 = att[i1] + ((p[i1] + p[i1 + S]) + (p[i1 + 2 * S] + p[i1 + 3 * S]));
    float m = block_sum256(x0 + x1, red) * (1.0f / 512.0f);
    float d0 = x0 - m, d1 = x1 - m;
    float v = block_sum256(d0 * d0 + d1 * d1, red) * (1.0f / 512.0f);
    float scale = 1.0f / sqrtf(v + 1e-5f);
    att[i0] = d0 * scale * g[l * HD_ + t]       + b[l * HD_ + t];
    att[i1] = d1 * scale * g[l * HD_ + t + 256] + b[l * HD_ + t + 256];
}

// ---------------- fused gumbel + argmax + uniform + output ----------------
__global__ __launch_bounds__(256) void sample_kernel(
    const float* __restrict__ logits, float* __restrict__ out,
    uint32_t kc0, uint32_t kc1, uint32_t ku0, uint32_t ku1)
{
    int warp = threadIdx.x >> 5, lane = threadIdx.x & 31;
    int j = blockIdx.x * 8 + warp;            // row in [B,V,N] flat, 0..16383
    int bv = j >> 5;
    const float* lg0 = &logits[bv * R_];
    const float* lg1 = lg0 + ROWS_ * R_;
    const float* lg2 = lg1 + ROWS_ * R_;
    const float* lg3 = lg2 + ROWS_ * R_;
    const float tiny = 1.17549435e-38f;
    float best = -__int_as_float(0x7f800000);
    int bidx = 0;
#pragma unroll
    for (int q = 0; q < 4; q++) {
        int r = lane + q * 32;
        float lgv = ((lg0[r] + lg1[r]) + lg2[r]) + lg3[r];
        uint32_t bits = jax_random_bits32(kc0, kc1, (uint32_t)(j * R_ + r));
        float u = fmaxf(bits_to_unit_float(bits), tiny);
        float gmb = -logf(-logf(u));
        float v = gmb + lgv;
        if (v > best) { best = v; bidx = r; }
    }
#pragma unroll
    for (int o = 16; o; o >>= 1) {
        float ov = __shfl_xor_sync(0xffffffffu, best, o);
        int   oi = __shfl_xor_sync(0xffffffffu, bidx, o);
        if (ov > best || (ov == best && oi < bidx)) { best = ov; bidx = oi; }
    }
    if (lane == 0) {
        uint32_t bits = jax_random_bits32(ku0, ku1, (uint32_t)j);
        float u = bits_to_unit_float(bits);
        out[j] = ((float)bidx + u) * (1.0f / 128.0f);
    }
}

// ---------------- launch ----------------
extern "C" void kernel_launch(void* const* d_in, const int* in_sizes, int n_in,
                              void* d_out, int out_size)
{
    int iflow = 0, iWshift = 1, ibshift = 2, iWk = 3, ibk = 4, iWv = 5, ibv = 6,
        iln1g = 7, iln1b = 8, iW1 = 9, ib1 = 10, iW2 = 11, ib2 = 12, iW3 = 13,
        ib3 = 14, iln2g = 15, iln2b = 16, iWdist = 17, ibdist = 18;
    if (in_sizes[0] == 2097152) {   // alphabetical fallback
        iW1 = 0; iW2 = 1; iW3 = 2; iWdist = 3; iWshift = 4; iWk = 5; iWv = 6;
        ib1 = 7; ib2 = 8; ib3 = 9; ibdist = 10; ibshift = 11; ibk = 12; ibv = 13;
        iflow = 14; iln1b = 15; iln1g = 16; iln2b = 17; iln2g = 18;
    }

    const float* flow    = (const float*)d_in[iflow];
    const float* W_shift = (const float*)d_in[iWshift];
    const float* b_shift = (const float*)d_in[ibshift];
    const float* Wk      = (const float*)d_in[iWk];
    const float* bk      = (const float*)d_in[ibk];
    const float* Wv      = (const float*)d_in[iWv];
    const float* bv      = (const float*)d_in[ibv];
    const float* ln1_g   = (const float*)d_in[iln1g];
    const float* ln1_b   = (const float*)d_in[iln1b];
    const float* W1      = (const float*)d_in[iW1];
    const float* b1      = (const float*)d_in[ib1];
    const float* W2      = (const float*)d_in[iW2];
    const float* b2      = (const float*)d_in[ib2];
    const float* W3      = (const float*)d_in[iW3];
    const float* b3      = (const float*)d_in[ib3];
    const float* ln2_g   = (const float*)d_in[iln2g];
    const float* ln2_b   = (const float*)d_in[iln2b];
    const float* W_dist  = (const float*)d_in[iWdist];
    const float* b_dist  = (const float*)d_in[ibdist];

    float *keysf, *valsf, *att, *h1, *h2, *h3, *logits;
    cudaGetSymbolAddress((void**)&keysf,  g_keysf);
    cudaGetSymbolAddress((void**)&valsf,  g_valsf);
    cudaGetSymbolAddress((void**)&att,    g_att);
    cudaGetSymbolAddress((void**)&h1,     g_h1);
    cudaGetSymbolAddress((void**)&h2,     g_h2);
    cudaGetSymbolAddress((void**)&h3,     g_h3);
    cudaGetSymbolAddress((void**)&logits, g_logits);

    uint32_t kc0, kc1, ku0, ku1;
    threefry2x32(0u, 1u, 0u, 0u, kc0, kc1);
    threefry2x32(0u, 1u, 0u, 1u, ku0, ku1);

    const int PH1 = ROWS_ * M_;     // partial stride h1/h2

    // keys + vals + att0 in one launch (576 blocks)
    qkv_kernel<<<576, 256>>>(flow, Wk, bk, Wv, bv, W_shift, b_shift,
                             keysf, valsf, att);

    for (int l = 0; l < L_; l++) {
        attn_ln_kernel<<<ROWS_, 256>>>(keysf, valsf, att, ln1_g, ln1_b, l);
        // h1 partials = att @ W1 (+b1 in z0); consumer applies relu(p0+p1)
        gemm_generic<<<dim3(16, 8, 2), 256>>>(att, nullptr,
                                              W1 + (size_t)l * HD_ * M_,
                                              b1 + l * M_, h1, HD_, M_);
        // h2 partials = relu(h1p0+h1p1) @ W2 (+b2 in z0)
        gemm_generic<<<dim3(16, 8, 2), 256>>>(h1, h1 + PH1,
                                              W2 + (size_t)l * M_ * M_,
                                              b2 + l * M_, h2, M_, M_);
        // h3 partials (z=4) = relu(h2p0+h2p1) @ W3 (+b3 in z0)
        gemm_generic<<<dim3(8, 8, 4), 256>>>(h2, h2 + PH1,
                                             W3 + (size_t)l * M_ * HD_,
                                             b3 + l * HD_, h3, M_, HD_);
        add_ln_kernel<<<ROWS_, 256>>>(h3, att, ln2_g, ln2_b, l);
    }

    // logits with split-K=4 (partials summed in sample_kernel)
    gemm_generic<<<dim3(2, 8, 4), 256>>>(att, nullptr, W_dist, b_dist,
                                         logits, HD_, R_);

    sample_kernel<<<2048, 256>>>(logits, (float*)d_out, kc0, kc1, ku0, ku1);
}

// round 5
// speedup vs baseline: 1.6115x; 1.0724x over previous
#include <cuda_runtime.h>
#include <cstdint>

// Problem dims (fixed by setup_inputs)
#define B_ 8
#define V_ 64
#define E_ 512
#define L_ 4
#define H_ 8
#define D_ 64
#define M_ 1024
#define R_ 128
#define HD_ 512
#define ROWS_ 512          // B*V
#define LHD_ 2048          // L*H*D

// GEMM tiling
#define BM 128
#define BN 128
#define BK 16
#define ASTRIDE 132

// ---------------- scratch (__device__ globals; no allocation) ----------------
__device__ __align__(16) float g_keysf[ROWS_ * LHD_];
__device__ __align__(16) float g_valsf[ROWS_ * LHD_];
__device__ __align__(16) float g_att[ROWS_ * HD_];
__device__ __align__(16) float g_h1[4 * ROWS_ * M_];      // 4 split-K partials
__device__ __align__(16) float g_h2[4 * ROWS_ * M_];      // 4 split-K partials
__device__ __align__(16) float g_h3[8 * ROWS_ * HD_];     // 8 split-K partials
__device__ __align__(16) float g_logits[8 * ROWS_ * R_];  // 8 split-K partials

// ---------------- threefry2x32 (exact JAX semantics) ----------------
__host__ __device__ __forceinline__ uint32_t rotl32(uint32_t x, int r) {
    return (x << r) | (x >> (32 - r));
}
__host__ __device__ __forceinline__ void threefry2x32(
    uint32_t k0, uint32_t k1, uint32_t c0, uint32_t c1,
    uint32_t& o0, uint32_t& o1)
{
    uint32_t ks0 = k0, ks1 = k1, ks2 = k0 ^ k1 ^ 0x1BD11BDAu;
    uint32_t x0 = c0 + ks0, x1 = c1 + ks1;
#define TFR(r) { x0 += x1; x1 = rotl32(x1, r); x1 ^= x0; }
    TFR(13) TFR(15) TFR(26) TFR(6)
    x0 += ks1; x1 += ks2 + 1u;
    TFR(17) TFR(29) TFR(16) TFR(24)
    x0 += ks2; x1 += ks0 + 2u;
    TFR(13) TFR(15) TFR(26) TFR(6)
    x0 += ks0; x1 += ks1 + 3u;
    TFR(17) TFR(29) TFR(16) TFR(24)
    x0 += ks1; x1 += ks2 + 4u;
    TFR(13) TFR(15) TFR(26) TFR(6)
    x0 += ks2; x1 += ks0 + 5u;
#undef TFR
    o0 = x0; o1 = x1;
}

__device__ __forceinline__ uint32_t jax_random_bits32(uint32_t k0, uint32_t k1, uint32_t i) {
    uint32_t o0, o1;
    threefry2x32(k0, k1, 0u, i, o0, o1);
    return o0 ^ o1;
}

__device__ __forceinline__ float bits_to_unit_float(uint32_t bits) {
    return __uint_as_float((bits >> 9) | 0x3f800000u) - 1.0f;
}

// ---------------- packed f32x2 helpers ----------------
__device__ __forceinline__ unsigned long long pack_dup(float a) {
    unsigned long long r;
    asm("mov.b64 %0, {%1, %1};" : "=l"(r) : "f"(a));
    return r;
}
__device__ __forceinline__ void ffma2(unsigned long long& acc,
                                      unsigned long long a, unsigned long long b) {
    asm("fma.rn.f32x2 %0, %1, %2, %0;" : "+l"(acc) : "l"(a), "l"(b));
}
__device__ __forceinline__ float2 unpack2(unsigned long long v) {
    float2 r;
    asm("mov.b64 {%0, %1}, %2;" : "=f"(r.x), "=f"(r.y) : "l"(v));
    return r;
}

// ---------------- A-load: plain, or fused relu(sum of NP partials) ----------------
template<int NP>
__device__ __forceinline__ float4 loadAf(const float* __restrict__ A, int offs, int sa) {
    float4 a = *(const float4*)&A[offs];
#pragma unroll
    for (int p = 1; p < NP; p++) {
        float4 b = *(const float4*)&A[offs + p * sa];
        a.x += b.x; a.y += b.y; a.z += b.z; a.w += b.w;
    }
    if (NP > 1) {
        a.x = fmaxf(a.x, 0.0f); a.y = fmaxf(a.y, 0.0f);
        a.z = fmaxf(a.z, 0.0f); a.w = fmaxf(a.w, 0.0f);
    }
    return a;
}

// ---------------- 128x128 double-buffered SGEMM body (f32x2, 8x8 microtile) ----------------
// W read through two pointers: cols [0,64) from Wp1, [64,128) from Wp2 (both stride ws).
template<int NP>
__device__ __forceinline__ void gemm_body(
    float (*As)[BK][ASTRIDE], float (*Ws)[BK][BN],
    const float* __restrict__ A, int sa, int lda,
    const float* __restrict__ Wp1, const float* __restrict__ Wp2, int ws,
    const float* __restrict__ bias, int useBias,
    float* __restrict__ C, int ldc,
    int row0, int n0, int kStart, int kLen)
{
    const int t  = threadIdx.x;
    const int ar = t >> 2, ac = (t & 3) << 2;       // A loader: rows ar, ar+64; k cols ac..ac+3
    const int wk = t >> 5, wn = (t & 31) << 2;      // W loader: k rows wk, wk+8; cols wn..wn+3
    const float* Wb = (wn < 64) ? Wp1 : Wp2;
    const int wc = wn & 63;

    const int aOff = (row0 + ar) * lda + kStart + ac;
    const float* Wp = Wb + (kStart + wk) * ws + wc;

    float4 a0 = loadAf<NP>(A, aOff, sa);
    float4 a1 = loadAf<NP>(A, aOff + 64 * lda, sa);
    float4 w0 = *(const float4*)Wp;
    float4 w1 = *(const float4*)(Wp + 8 * ws);

    As[0][ac + 0][ar] = a0.x; As[0][ac + 1][ar] = a0.y;
    As[0][ac + 2][ar] = a0.z; As[0][ac + 3][ar] = a0.w;
    As[0][ac + 0][ar + 64] = a1.x; As[0][ac + 1][ar + 64] = a1.y;
    As[0][ac + 2][ar + 64] = a1.z; As[0][ac + 3][ar + 64] = a1.w;
    *(float4*)&Ws[0][wk][wn]     = w0;
    *(float4*)&Ws[0][wk + 8][wn] = w1;
    __syncthreads();

    const int tx = t & 15, ty = t >> 4;             // compute: rows ty*8..+7, cols tx*4 & 64+tx*4
    unsigned long long acc2[8][4];
#pragma unroll
    for (int i = 0; i < 8; i++)
#pragma unroll
        for (int j = 0; j < 4; j++) acc2[i][j] = 0ull;

    const int nIter = kLen >> 4;
    int buf = 0;
    for (int it = 0; it < nIter; ++it) {
        if (it + 1 < nIter) {
            int o2 = aOff + ((it + 1) << 4);
            a0 = loadAf<NP>(A, o2, sa);
            a1 = loadAf<NP>(A, o2 + 64 * lda, sa);
            const float* Wn = Wp + ((it + 1) << 4) * ws;
            w0 = *(const float4*)Wn;
            w1 = *(const float4*)(Wn + 8 * ws);
        }
#pragma unroll
        for (int k = 0; k < BK; ++k) {
            float4 av0 = *(const float4*)&As[buf][k][ty * 8];
            float4 av1 = *(const float4*)&As[buf][k][ty * 8 + 4];
            ulonglong2 bv0 = *(const ulonglong2*)&Ws[buf][k][tx * 4];
            ulonglong2 bv1 = *(const ulonglong2*)&Ws[buf][k][64 + tx * 4];
            unsigned long long a2[8];
            a2[0] = pack_dup(av0.x); a2[1] = pack_dup(av0.y);
            a2[2] = pack_dup(av0.z); a2[3] = pack_dup(av0.w);
            a2[4] = pack_dup(av1.x); a2[5] = pack_dup(av1.y);
            a2[6] = pack_dup(av1.z); a2[7] = pack_dup(av1.w);
#pragma unroll
            for (int i = 0; i < 8; i++) {
                ffma2(acc2[i][0], a2[i], bv0.x);
                ffma2(acc2[i][1], a2[i], bv0.y);
                ffma2(acc2[i][2], a2[i], bv1.x);
                ffma2(acc2[i][3], a2[i], bv1.y);
            }
        }
        if (it + 1 < nIter) {
            int nb = buf ^ 1;
            As[nb][ac + 0][ar] = a0.x; As[nb][ac + 1][ar] = a0.y;
            As[nb][ac + 2][ar] = a0.z; As[nb][ac + 3][ar] = a0.w;
            As[nb][ac + 0][ar + 64] = a1.x; As[nb][ac + 1][ar + 64] = a1.y;
            As[nb][ac + 2][ar + 64] = a1.z; As[nb][ac + 3][ar + 64] = a1.w;
            *(float4*)&Ws[nb][wk][wn]     = w0;
            *(float4*)&Ws[nb][wk + 8][wn] = w1;
            __syncthreads();
            buf = nb;
        }
    }

#pragma unroll
    for (int i = 0; i < 8; i++) {
        int r = row0 + ty * 8 + i;
#pragma unroll
        for (int g = 0; g < 2; g++) {
            int n = n0 + g * 64 + tx * 4;
            float2 p0 = unpack2(acc2[i][2 * g]);
            float2 p1 = unpack2(acc2[i][2 * g + 1]);
            float4 v = make_float4(p0.x, p0.y, p1.x, p1.y);
            if (useBias) {
                v.x += bias[n];     v.y += bias[n + 1];
                v.z += bias[n + 2]; v.w += bias[n + 3];
            }
            *(float4*)&C[r * ldc + n] = v;
        }
    }
}

// ---------------- generic GEMM kernel (split-K via grid.z) ----------------
template<int NP>
__global__ __launch_bounds__(256) void gemm128(
    const float* __restrict__ A, int sa,
    const float* __restrict__ W,
    const float* __restrict__ bias, float* __restrict__ C,
    int K, int N)
{
    __shared__ float As[2][BK][ASTRIDE];
    __shared__ float Ws[2][BK][BN];
    int n0 = blockIdx.x * BN, row0 = blockIdx.y * BM;
    int z = blockIdx.z;
    int kLen = K / gridDim.z;
    float* Cz = C + (size_t)z * (ROWS_ * N);
    gemm_body<NP>(As, Ws, A, sa, K, W + n0, W + n0 + 64, N,
                  bias, (z == 0) ? 1 : 0, Cz, N, row0, n0, z * kLen, kLen);
}

// ---------------- merged keys/vals/att0 kernel (144 blocks) ----------------
__global__ __launch_bounds__(256) void qkv_kernel(
    const float* __restrict__ flow,
    const float* __restrict__ Wk, const float* __restrict__ bk,
    const float* __restrict__ Wv, const float* __restrict__ bv,
    const float* __restrict__ Wsh, const float* __restrict__ bsh,
    float* __restrict__ keys, float* __restrict__ vals, float* __restrict__ att)
{
    __shared__ float As[2][BK][ASTRIDE];
    __shared__ float Ws[2][BK][BN];
    int bid = blockIdx.x;
    if (bid < 128) {                              // keys (0..63) / vals (64..127)
        int isV = bid >> 6;
        int j = bid & 63;
        int rt = j >> 4, nt = j & 15;             // 4 row tiles x 16 col tiles
        const float* Wsel = isV ? Wv : Wk;        // [L*H][E][64]
        const float* Wp1 = Wsel + (size_t)(2 * nt)     * E_ * 64;
        const float* Wp2 = Wsel + (size_t)(2 * nt + 1) * E_ * 64;
        gemm_body<1>(As, Ws, flow, 0, E_, Wp1, Wp2, 64,
                     isV ? bv : bk, 1, isV ? vals : keys, LHD_,
                     rt * BM, nt * BN, 0, E_);
    } else {                                      // att0 (128..143)
        int j = bid - 128;
        int rt = j >> 2, nt = j & 3;              // 4 x 4
        gemm_body<1>(As, Ws, flow, 0, E_,
                     Wsh + nt * BN, Wsh + nt * BN + 64, HD_,
                     bsh, 1, att, HD_, rt * BM, nt * BN, 0, E_);
    }
}

// ---------------- block sum over 256 threads ----------------
__device__ __forceinline__ float block_sum256(float v, float* red) {
#pragma unroll
    for (int o = 16; o; o >>= 1) v += __shfl_xor_sync(0xffffffffu, v, o);
    int w = threadIdx.x >> 5;
    if ((threadIdx.x & 31) == 0) red[w] = v;
    __syncthreads();
    float tot = 0.0f;
#pragma unroll
    for (int k = 0; k < 8; k++) tot += red[k];
    __syncthreads();
    return tot;
}

// ---------------- attention + residual + LN1 (per (b,v) row) ----------------
__global__ __launch_bounds__(256) void attn_ln_kernel(
    const float* __restrict__ keysf, const float* __restrict__ valsf,
    float* __restrict__ att,
    const float* __restrict__ g, const float* __restrict__ b, int l)
{
    int row = blockIdx.x;             // 0..511 = b*V+v
    int bId = row >> 6;
    int t = threadIdx.x;
    __shared__ float qs[HD_];
    __shared__ float sp[HD_];
    __shared__ float red[8];

    qs[t]       = att[row * HD_ + t];
    qs[t + 256] = att[row * HD_ + t + 256];
    __syncthreads();

    int h = t >> 5, lane = t & 31;
    float s[2];
#pragma unroll
    for (int ww = 0; ww < 2; ww++) {
        int w = lane + ww * 32;
        const float* kp = &keysf[(bId * V_ + w) * LHD_ + (l * H_ + h) * D_];
        float accv = 0.0f;
#pragma unroll
        for (int d = 0; d < 64; d++) accv = fmaf(qs[h * 64 + d], kp[d], accv);
        s[ww] = accv * 0.125f;
    }
    float mx = fmaxf(s[0], s[1]);
#pragma unroll
    for (int o = 16; o; o >>= 1) mx = fmaxf(mx, __shfl_xor_sync(0xffffffffu, mx, o));
    float e0 = expf(s[0] - mx), e1 = expf(s[1] - mx);
    float sum = e0 + e1;
#pragma unroll
    for (int o = 16; o; o >>= 1) sum += __shfl_xor_sync(0xffffffffu, sum, o);
    sp[h * 64 + lane]      = e0 / sum;
    sp[h * 64 + lane + 32] = e1 / sum;
    __syncthreads();

    float r[2];
#pragma unroll
    for (int rep = 0; rep < 2; rep++) {
        int hd = t + rep * 256;
        int hh = hd >> 6, d = hd & 63;
        const float* vp = &valsf[(bId * V_) * LHD_ + (l * H_ + hh) * D_ + d];
        float accv = 0.0f;
#pragma unroll
        for (int w = 0; w < 64; w++) accv = fmaf(sp[hh * 64 + w], vp[w * LHD_], accv);
        r[rep] = qs[hd] + accv;
    }
    __syncthreads();

    float m = block_sum256(r[0] + r[1], red) * (1.0f / 512.0f);
    float d0 = r[0] - m, d1 = r[1] - m;
    float v = block_sum256(d0 * d0 + d1 * d1, red) * (1.0f / 512.0f);
    float scale = 1.0f / sqrtf(v + 1e-5f);
    att[row * HD_ + t]       = d0 * scale * g[l * HD_ + t]       + b[l * HD_ + t];
    att[row * HD_ + t + 256] = d1 * scale * g[l * HD_ + t + 256] + b[l * HD_ + t + 256];
}

// ---------------- residual (8 split-K partials) + LN2 ----------------
__global__ __launch_bounds__(256) void add_ln_kernel(
    const float* __restrict__ p, float* __restrict__ att,
    const float* __restrict__ g, const float* __restrict__ b, int l)
{
    int row = blockIdx.x;
    int t = threadIdx.x;
    __shared__ float red[8];
    const int S = ROWS_ * HD_;
    int i0 = row * HD_ + t, i1 = i0 + 256;
    float x0 = att[i0], x1 = att[i1];
#pragma unroll
    for (int q = 0; q < 8; q++) { x0 += p[i0 + q * S]; x1 += p[i1 + q * S]; }
    float m = block_sum256(x0 + x1, red) * (1.0f / 512.0f);
    float d0 = x0 - m, d1 = x1 - m;
    float v = block_sum256(d0 * d0 + d1 * d1, red) * (1.0f / 512.0f);
    float scale = 1.0f / sqrtf(v + 1e-5f);
    att[i0] = d0 * scale * g[l * HD_ + t]       + b[l * HD_ + t];
    att[i1] = d1 * scale * g[l * HD_ + t + 256] + b[l * HD_ + t + 256];
}

// ---------------- fused gumbel + argmax + uniform + output ----------------
__global__ __launch_bounds__(256) void sample_kernel(
    const float* __restrict__ logits, float* __restrict__ out,
    uint32_t kc0, uint32_t kc1, uint32_t ku0, uint32_t ku1)
{
    int warp = threadIdx.x >> 5, lane = threadIdx.x & 31;
    int j = blockIdx.x * 8 + warp;            // row in [B,V,N] flat, 0..16383
    int bv = j >> 5;
    const int SL = ROWS_ * R_;
    const float tiny = 1.17549435e-38f;
    float best = -__int_as_float(0x7f800000);
    int bidx = 0;
#pragma unroll
    for (int q = 0; q < 4; q++) {
        int r = lane + q * 32;
        float lgv = 0.0f;
#pragma unroll
        for (int z = 0; z < 8; z++) lgv += logits[z * SL + bv * R_ + r];
        uint32_t bits = jax_random_bits32(kc0, kc1, (uint32_t)(j * R_ + r));
        float u = fmaxf(bits_to_unit_float(bits), tiny);
        float gmb = -logf(-logf(u));
        float v = gmb + lgv;
        if (v > best) { best = v; bidx = r; }
    }
#pragma unroll
    for (int o = 16; o; o >>= 1) {
        float ov = __shfl_xor_sync(0xffffffffu, best, o);
        int   oi = __shfl_xor_sync(0xffffffffu, bidx, o);
        if (ov > best || (ov == best && oi < bidx)) { best = ov; bidx = oi; }
    }
    if (lane == 0) {
        uint32_t bits = jax_random_bits32(ku0, ku1, (uint32_t)j);
        float u = bits_to_unit_float(bits);
        out[j] = ((float)bidx + u) * (1.0f / 128.0f);
    }
}

// ---------------- launch ----------------
extern "C" void kernel_launch(void* const* d_in, const int* in_sizes, int n_in,
                              void* d_out, int out_size)
{
    int iflow = 0, iWshift = 1, ibshift = 2, iWk = 3, ibk = 4, iWv = 5, ibv = 6,
        iln1g = 7, iln1b = 8, iW1 = 9, ib1 = 10, iW2 = 11, ib2 = 12, iW3 = 13,
        ib3 = 14, iln2g = 15, iln2b = 16, iWdist = 17, ibdist = 18;
    if (in_sizes[0] == 2097152) {   // alphabetical fallback
        iW1 = 0; iW2 = 1; iW3 = 2; iWdist = 3; iWshift = 4; iWk = 5; iWv = 6;
        ib1 = 7; ib2 = 8; ib3 = 9; ibdist = 10; ibshift = 11; ibk = 12; ibv = 13;
        iflow = 14; iln1b = 15; iln1g = 16; iln2b = 17; iln2g = 18;
    }

    const float* flow    = (const float*)d_in[iflow];
    const float* W_shift = (const float*)d_in[iWshift];
    const float* b_shift = (const float*)d_in[ibshift];
    const float* Wk      = (const float*)d_in[iWk];
    const float* bk      = (const float*)d_in[ibk];
    const float* Wv      = (const float*)d_in[iWv];
    const float* bv      = (const float*)d_in[ibv];
    const float* ln1_g   = (const float*)d_in[iln1g];
    const float* ln1_b   = (const float*)d_in[iln1b];
    const float* W1      = (const float*)d_in[iW1];
    const float* b1      = (const float*)d_in[ib1];
    const float* W2      = (const float*)d_in[iW2];
    const float* b2      = (const float*)d_in[ib2];
    const float* W3      = (const float*)d_in[iW3];
    const float* b3      = (const float*)d_in[ib3];
    const float* ln2_g   = (const float*)d_in[iln2g];
    const float* ln2_b   = (const float*)d_in[iln2b];
    const float* W_dist  = (const float*)d_in[iWdist];
    const float* b_dist  = (const float*)d_in[ibdist];

    float *keysf, *valsf, *att, *h1, *h2, *h3, *logits;
    cudaGetSymbolAddress((void**)&keysf,  g_keysf);
    cudaGetSymbolAddress((void**)&valsf,  g_valsf);
    cudaGetSymbolAddress((void**)&att,    g_att);
    cudaGetSymbolAddress((void**)&h1,     g_h1);
    cudaGetSymbolAddress((void**)&h2,     g_h2);
    cudaGetSymbolAddress((void**)&h3,     g_h3);
    cudaGetSymbolAddress((void**)&logits, g_logits);

    uint32_t kc0, kc1, ku0, ku1;
    threefry2x32(0u, 1u, 0u, 0u, kc0, kc1);
    threefry2x32(0u, 1u, 0u, 1u, ku0, ku1);

    const int PH1 = ROWS_ * M_;   // partial stride for h1/h2

    // keys + vals + att0 in one launch (144 blocks of 128x128 tiles)
    qkv_kernel<<<144, 256>>>(flow, Wk, bk, Wv, bv, W_shift, b_shift,
                             keysf, valsf, att);

    for (int l = 0; l < L_; l++) {
        attn_ln_kernel<<<ROWS_, 256>>>(keysf, valsf, att, ln1_g, ln1_b, l);
        // h1 partials (z=4) = att @ W1 (+b1 in z0)
        gemm128<1><<<dim3(8, 4, 4), 256>>>(att, 0, W1 + (size_t)l * HD_ * M_,
                                           b1 + l * M_, h1, HD_, M_);
        // h2 partials (z=4) = relu(sum4 h1) @ W2 (+b2 in z0)
        gemm128<4><<<dim3(8, 4, 4), 256>>>(h1, PH1, W2 + (size_t)l * M_ * M_,
                                           b2 + l * M_, h2, M_, M_);
        // h3 partials (z=8) = relu(sum4 h2) @ W3 (+b3 in z0)
        gemm128<4><<<dim3(4, 4, 8), 256>>>(h2, PH1, W3 + (size_t)l * M_ * HD_,
                                           b3 + l * HD_, h3, M_, HD_);
        add_ln_kernel<<<ROWS_, 256>>>(h3, att, ln2_g, ln2_b, l);
    }

    // logits partials (z=8) = att @ W_dist (+b_dist in z0); sample sums 8
    gemm128<1><<<dim3(1, 4, 8), 256>>>(att, 0, W_dist, b_dist, logits, HD_, R_);

    sample_kernel<<<2048, 256>>>(logits, (float*)d_out, kc0, kc1, ku0, ku1);
}